// round 11
// baseline (speedup 1.0000x reference)
#include <cuda_runtime.h>

typedef unsigned long long ull;

#define NB    16
#define SLEN  2048
#define NTOK  (NB * SLEN)
#define HDIM  256
#define FDIM  512
#define NREC  (SLEN / 2)   // key-pair records
#define FREC  (FDIM / 2)   // ffn-pair records
#define LOG2E 1.4426950408889634f

struct LayerConsts {
    float A2[16];   // log2e*bw^2 * Wq Wk^T
    float M2[16];   // 0.5*log2e*bw^2 * Wk Wk^T
    float Cm[16];   // Wv Wo
    float cvec[4];  // log2e*bw^2 * (Wk bq - Wk bk)
    float d0[4];    // Wo^T bv + bo
    float cconst;   // log2e*bw^2 * (bq.bk - 0.5|bk|^2)
};
#define LC_FLOATS (int)(sizeof(LayerConsts) * 2 / 4)

__device__ float4 d_X[NTOK];
__device__ float  d_c[NTOK];
__device__ LayerConsts d_cg[2];   // written by k_att<0> CTA(0,0), read by k_att<1>

// ---------------- packed fp32x2 helpers ----------------
__device__ __forceinline__ ull fma2(ull a, ull b, ull c) {
    ull d; asm("fma.rn.f32x2 %0, %1, %2, %3;" : "=l"(d) : "l"(a), "l"(b), "l"(c)); return d;
}
__device__ __forceinline__ ull add2(ull a, ull b) {
    ull d; asm("add.rn.f32x2 %0, %1, %2;" : "=l"(d) : "l"(a), "l"(b)); return d;
}
__device__ __forceinline__ ull pk2(float lo, float hi) {
    ull r; asm("mov.b64 %0, {%1, %2};" : "=l"(r) : "f"(lo), "f"(hi)); return r;
}
__device__ __forceinline__ float2 upk2(ull x) {
    float2 r; asm("mov.b64 {%0, %1}, %2;" : "=f"(r.x), "=f"(r.y) : "l"(x)); return r;
}
__device__ __forceinline__ float fast_exp2(float x) {
    float r; asm("ex2.approx.ftz.f32 %0, %1;" : "=f"(r) : "f"(x)); return r;
}

// per-key logit constant c = cconst + sum_i (cvec_i - (M2 x)_i) x_i
__device__ __forceinline__ float cfeat(const LayerConsts& C, float4 xv)
{
    float x[4] = {xv.x, xv.y, xv.z, xv.w};
    float c = C.cconst;
    #pragma unroll
    for (int i = 0; i < 4; ++i) {
        float mi = 0.f;
        #pragma unroll
        for (int j = 0; j < 4; ++j) mi = fmaf(C.M2[i * 4 + j], x[j], mi);
        c = fmaf(C.cvec[i] - mi, x[i], c);
    }
    return c;
}

__device__ __forceinline__ void ln4(float h[4], const float* __restrict__ g,
                                    const float* __restrict__ be, int l)
{
    float mean = 0.25f * (h[0] + h[1] + h[2] + h[3]);
    float e0 = h[0] - mean, e1 = h[1] - mean, e2 = h[2] - mean, e3 = h[3] - mean;
    float var = 0.25f * (e0 * e0 + e1 * e1 + e2 * e2 + e3 * e3);
    float r = rsqrtf(var + 1e-5f);
    h[0] = fmaf(e0 * r, g[l * 4 + 0], be[l * 4 + 0]);
    h[1] = fmaf(e1 * r, g[l * 4 + 1], be[l * 4 + 1]);
    h[2] = fmaf(e2 * r, g[l * 4 + 2], be[l * 4 + 2]);
    h[3] = fmaf(e3 * r, g[l * 4 + 3], be[l * 4 + 3]);
}

// ---------------------------------------------------------------------------
// Fused attention + LN1 + FFN + LN2 (+ next-layer feat / final fc).
// grid (32, 16), 128 threads (4 warps), tile = 64 queries.
//
// ATTENTION IS WARP-COOPERATIVE: warp w owns queries [w*16, w*16+16) of the
// tile, processed in 4 groups of 4 concurrent queries. Within a group, lane L
// iterates records it*32+L (lane-strided smem, conflict-free, NO broadcast
// redundancy -> 32x less smem crossbar traffic than query-per-thread), and
// accumulates all 4 queries' packed partials. Cross-lane shfl reduction
// publishes (sum, a0..a3) per query to sRed.
//
// Epilogue (LN1+FFN+LN2) stays query-per-thread: (qid = tid&63, half=tid>>6).
// LAYER 0 computes the 4x4 layer constants per-CTA and CTA(0,0) publishes
// them to d_cg; LAYER 1 copies them.
// True logit <= 0 (max exactly 0 on the diagonal); per-query softmax-
// invariant shift cancels in normalization -> no max pass, no overflow.
// ---------------------------------------------------------------------------
#define SMEM_BYTES (NREC * 40)
static_assert(FREC * 16 * 4 + FREC * 8 <= SMEM_BYTES, "ffn overlay exceeds key smem");

template <int LAYER>
__global__ void __launch_bounds__(128, 4)
k_att(const float* __restrict__ KEY, const float* __restrict__ VAL,
      float* __restrict__ out,
      const float* __restrict__ Wq, const float* __restrict__ bq,
      const float* __restrict__ Wk, const float* __restrict__ bk,
      const float* __restrict__ Wv, const float* __restrict__ bv,
      const float* __restrict__ Wo, const float* __restrict__ bo,
      const float* __restrict__ bw,
      const float* __restrict__ g1, const float* __restrict__ be1,
      const float* __restrict__ W1, const float* __restrict__ b1,
      const float* __restrict__ W2, const float* __restrict__ b2,
      const float* __restrict__ g2, const float* __restrict__ be2,
      const float* __restrict__ Wfc, const float* __restrict__ bfc)
{
    __shared__ __align__(16) unsigned char smraw[SMEM_BYTES];   // 40960 B
    __shared__ float sRed[64 * 5];
    __shared__ float sAcc[124];        // raw contraction outputs (2 layers x 62)
    __shared__ LayerConsts sCs[2];

    ulonglong2* sKA = (ulonglong2*)smraw;
    ulonglong2* sKB = (ulonglong2*)(smraw + NREC * 16);
    ull*        sKC = (ull*)(smraw + NREC * 32);
    // FFN overlay (written after attention phase): 18 KB
    ulonglong2* sF1 = (ulonglong2*)smraw;
    ulonglong2* sF2 = sF1 + FREC;
    ulonglong2* sF3 = sF2 + FREC;
    ulonglong2* sF4 = sF3 + FREC;
    ull*        sFB = (ull*)(sF4 + FREC);

    int tid  = threadIdx.x;
    int qid  = tid & 63;
    int half = tid >> 6;
    int w = tid >> 5, lane = tid & 31;
    int base = blockIdx.y * SLEN;
    int tile0 = blockIdx.x * 64;

    if (LAYER == 0) {
        // ---- prologue: layer constants, warp-per-task outer products ----
        #pragma unroll
        for (int pass = 0; pass < 2; ++pass) {
            int t = w + 4 * pass;
            int l = t >> 2, type = t & 3;
            const float* wqp = Wq + l * 4 * HDIM;
            const float* wkp = Wk + l * 4 * HDIM;
            const float* wvp = Wv + l * 4 * HDIM;
            const float* wop = Wo + l * HDIM * 4;
            const float* bqp = bq + l * HDIM;
            const float* bkp = bk + l * HDIM;
            const float* bvp = bv + l * HDIM;

            float av[16];
            #pragma unroll
            for (int i = 0; i < 16; ++i) av[i] = 0.f;

            if (type == 0) {
                #pragma unroll
                for (int c = 0; c < 8; ++c) {
                    int h = lane + 32 * c;
                    float a[4], b[4];
                    #pragma unroll
                    for (int i = 0; i < 4; ++i) { a[i] = wqp[i * HDIM + h]; b[i] = wkp[i * HDIM + h]; }
                    #pragma unroll
                    for (int i = 0; i < 4; ++i)
                        #pragma unroll
                        for (int j = 0; j < 4; ++j) av[i * 4 + j] = fmaf(a[i], b[j], av[i * 4 + j]);
                }
            } else if (type == 1) {
                #pragma unroll
                for (int c = 0; c < 8; ++c) {
                    int h = lane + 32 * c;
                    float b[4];
                    #pragma unroll
                    for (int i = 0; i < 4; ++i) b[i] = wkp[i * HDIM + h];
                    #pragma unroll
                    for (int i = 0; i < 4; ++i)
                        #pragma unroll
                        for (int j = 0; j < 4; ++j) av[i * 4 + j] = fmaf(b[i], b[j], av[i * 4 + j]);
                }
            } else if (type == 2) {
                #pragma unroll
                for (int c = 0; c < 8; ++c) {
                    int h = lane + 32 * c;
                    float a[4], b[4];
                    #pragma unroll
                    for (int i = 0; i < 4; ++i) { a[i] = wvp[i * HDIM + h]; b[i] = wop[h * 4 + i]; }
                    #pragma unroll
                    for (int i = 0; i < 4; ++i)
                        #pragma unroll
                        for (int j = 0; j < 4; ++j) av[i * 4 + j] = fmaf(a[i], b[j], av[i * 4 + j]);
                }
            } else {
                #pragma unroll
                for (int c = 0; c < 8; ++c) {
                    int h = lane + 32 * c;
                    float kvv[4], ov[4];
                    #pragma unroll
                    for (int i = 0; i < 4; ++i) { kvv[i] = wkp[i * HDIM + h]; ov[i] = wop[h * 4 + i]; }
                    float bqv = bqp[h], bkv = bkp[h], bvv = bvp[h];
                    #pragma unroll
                    for (int i = 0; i < 4; ++i) {
                        av[i]     = fmaf(kvv[i], bqv, av[i]);
                        av[4 + i] = fmaf(kvv[i], bkv, av[4 + i]);
                        av[8 + i] = fmaf(bvv, ov[i], av[8 + i]);
                    }
                    av[12] = fmaf(bqv, bkv, av[12]);
                    av[13] = fmaf(bkv, bkv, av[13]);
                }
            }

            #pragma unroll
            for (int i = 0; i < 16; ++i) {
                float s = av[i];
                s += __shfl_xor_sync(0xffffffffu, s, 16);
                s += __shfl_xor_sync(0xffffffffu, s, 8);
                s += __shfl_xor_sync(0xffffffffu, s, 4);
                s += __shfl_xor_sync(0xffffffffu, s, 2);
                s += __shfl_xor_sync(0xffffffffu, s, 1);
                av[i] = s;
            }
            if (lane == 0) {
                int nout = (type == 3) ? 14 : 16;
                int obase = 62 * l + type * 16;   // type 3 -> 48
                #pragma unroll
                for (int i = 0; i < 16; ++i)
                    if (i < nout) sAcc[obase + i] = av[i];
            }
        }
        __syncthreads();
        if (tid < 64) {
            int l = tid >> 5, sub = tid & 31;
            const float* accL = sAcc + 62 * l;
            float sc = LOG2E * bw[l] * bw[l];
            LayerConsts* C = &sCs[l];
            if (sub < 16) {
                C->A2[sub] = sc * accL[sub];
                C->M2[sub] = 0.5f * sc * accL[16 + sub];
                C->Cm[sub] = accL[32 + sub];
            } else if (sub < 20) {
                int i = sub - 16;
                C->cvec[i] = sc * (accL[48 + i] - accL[52 + i]);
                C->d0[i]   = accL[56 + i] + bo[l * 4 + i];
            } else if (sub == 20) {
                C->cconst = sc * (accL[60] - 0.5f * accL[61]);
            }
        }
        __syncthreads();
        if (blockIdx.x == 0 && blockIdx.y == 0 && tid < LC_FLOATS)
            ((float*)d_cg)[tid] = ((const float*)sCs)[tid];
    } else {
        if (tid < LC_FLOATS)
            ((float*)sCs)[tid] = ((const float*)d_cg)[tid];
        __syncthreads();
    }

    const LayerConsts& Cs = sCs[LAYER];

    // ---- prefill key pairs (all 128 threads) ----
    for (int r = tid; r < NREC; r += 128) {
        int t0 = base + 2 * r;
        float4 x0, x1; float c0, c1;
        if (LAYER == 0) {
            x0 = make_float4(KEY[3 * t0], KEY[3 * t0 + 1], KEY[3 * t0 + 2], VAL[t0]);
            x1 = make_float4(KEY[3 * t0 + 3], KEY[3 * t0 + 4], KEY[3 * t0 + 5], VAL[t0 + 1]);
            c0 = cfeat(Cs, x0);
            c1 = cfeat(Cs, x1);
        } else {
            x0 = d_X[t0]; x1 = d_X[t0 + 1];
            c0 = d_c[t0]; c1 = d_c[t0 + 1];
        }
        sKA[r] = make_ulonglong2(pk2(x0.x, x1.x), pk2(x0.y, x1.y));
        sKB[r] = make_ulonglong2(pk2(x0.z, x1.z), pk2(x0.w, x1.w));
        sKC[r] = pk2(c0, c1);
    }
    __syncthreads();

    // ---- attention: warp-cooperative, 4 queries per group, lanes over keys ----
    #pragma unroll 1
    for (int g = 0; g < 4; ++g) {
        int qb = base + tile0 + w * 16 + g * 4;

        // folded logit vectors for the 4 queries (all lanes compute; cheap)
        ull gq[4][4];
        #pragma unroll
        for (int j = 0; j < 4; ++j) {
            float4 xj;
            if (LAYER == 0) {
                int t = qb + j;
                xj = make_float4(KEY[3 * t], KEY[3 * t + 1], KEY[3 * t + 2], VAL[t]);
            } else {
                xj = d_X[qb + j];
            }
            float q0 = xj.x * Cs.A2[0] + xj.y * Cs.A2[4] + xj.z * Cs.A2[8]  + xj.w * Cs.A2[12];
            float q1 = xj.x * Cs.A2[1] + xj.y * Cs.A2[5] + xj.z * Cs.A2[9]  + xj.w * Cs.A2[13];
            float q2 = xj.x * Cs.A2[2] + xj.y * Cs.A2[6] + xj.z * Cs.A2[10] + xj.w * Cs.A2[14];
            float q3 = xj.x * Cs.A2[3] + xj.y * Cs.A2[7] + xj.z * Cs.A2[11] + xj.w * Cs.A2[15];
            gq[j][0] = pk2(q0, q0);
            gq[j][1] = pk2(q1, q1);
            gq[j][2] = pk2(q2, q2);
            gq[j][3] = pk2(q3, q3);
        }

        ull acc[4][5];
        #pragma unroll
        for (int j = 0; j < 4; ++j)
            #pragma unroll
            for (int k = 0; k < 5; ++k) acc[j][k] = 0ull;

        // lane-strided sweep over all 1024 records (2048 keys)
        #pragma unroll 1
        for (int it = 0; it < NREC / 32; ++it) {
            int r = it * 32 + lane;
            ulonglong2 A = sKA[r];
            ulonglong2 B = sKB[r];
            ull Cc = sKC[r];
            #pragma unroll
            for (int j = 0; j < 4; ++j) {
                ull lg = fma2(gq[j][0], A.x, Cc);
                lg = fma2(gq[j][1], A.y, lg);
                lg = fma2(gq[j][2], B.x, lg);
                lg = fma2(gq[j][3], B.y, lg);
                float2 lf = upk2(lg);
                ull pp = pk2(fast_exp2(lf.x), fast_exp2(lf.y));
                acc[j][0] = add2(acc[j][0], pp);
                acc[j][1] = fma2(pp, A.x, acc[j][1]);
                acc[j][2] = fma2(pp, A.y, acc[j][2]);
                acc[j][3] = fma2(pp, B.x, acc[j][3]);
                acc[j][4] = fma2(pp, B.y, acc[j][4]);
            }
        }

        // cross-lane reduction + publish
        #pragma unroll
        for (int j = 0; j < 4; ++j) {
            float red[5];
            #pragma unroll
            for (int k = 0; k < 5; ++k) {
                float2 hh = upk2(acc[j][k]);
                float v = hh.x + hh.y;
                v += __shfl_xor_sync(0xffffffffu, v, 16);
                v += __shfl_xor_sync(0xffffffffu, v, 8);
                v += __shfl_xor_sync(0xffffffffu, v, 4);
                v += __shfl_xor_sync(0xffffffffu, v, 2);
                v += __shfl_xor_sync(0xffffffffu, v, 1);
                red[k] = v;
            }
            if (lane == j) {
                int ql = w * 16 + g * 4 + j;
                #pragma unroll
                for (int k = 0; k < 5; ++k) sRed[ql * 5 + k] = red[k];
            }
        }
    }
    __syncthreads();   // (A) attn done; partials in sRed; key smem dead

    // FFN weight overlay straight from global: 2 records per thread
    for (int i = tid; i < FREC; i += 128) {
        int f = 2 * i;
        const float* w1 = W1 + LAYER * 4 * FDIM;
        const float* w2 = W2 + LAYER * FDIM * 4;
        float2 u0 = *(const float2*)(w1 + 0 * FDIM + f);
        float2 u1 = *(const float2*)(w1 + 1 * FDIM + f);
        float2 u2 = *(const float2*)(w1 + 2 * FDIM + f);
        float2 u3 = *(const float2*)(w1 + 3 * FDIM + f);
        float2 bb = *(const float2*)(b1 + LAYER * FDIM + f);
        float4 r0v = *(const float4*)(w2 + f * 4);
        float4 r1v = *(const float4*)(w2 + (f + 1) * 4);
        sF1[i] = make_ulonglong2(pk2(u0.x, u0.y), pk2(u1.x, u1.y));
        sF2[i] = make_ulonglong2(pk2(u2.x, u2.y), pk2(u3.x, u3.y));
        sFB[i] = pk2(bb.x, bb.y);
        sF3[i] = make_ulonglong2(pk2(r0v.x, r1v.x), pk2(r0v.y, r1v.y));
        sF4[i] = make_ulonglong2(pk2(r0v.z, r1v.z), pk2(r0v.w, r1v.w));
    }

    int q = base + tile0 + qid;
    float4 xq;
    float r0, r1, r2, r3;
    if (!half) {
        if (LAYER == 0)
            xq = make_float4(KEY[3 * q], KEY[3 * q + 1], KEY[3 * q + 2], VAL[q]);
        else
            xq = d_X[q];
        float ps  = sRed[qid * 5 + 0];
        float pa0 = sRed[qid * 5 + 1];
        float pa1 = sRed[qid * 5 + 2];
        float pa2 = sRed[qid * 5 + 3];
        float pa3 = sRed[qid * 5 + 4];
        float inv = 1.0f / ps;
        float h[4];
        #pragma unroll
        for (int j = 0; j < 4; ++j) {
            float vj = pa0 * Cs.Cm[0 * 4 + j] + pa1 * Cs.Cm[1 * 4 + j]
                     + pa2 * Cs.Cm[2 * 4 + j] + pa3 * Cs.Cm[3 * 4 + j];
            h[j] = ((&xq.x)[j]) + fmaf(vj, inv, Cs.d0[j]);
        }
        ln4(h, g1, be1, LAYER);
        r0 = h[0]; r1 = h[1]; r2 = h[2]; r3 = h[3];
        sRed[qid * 5 + 0] = r0;
        sRed[qid * 5 + 1] = r1;
        sRed[qid * 5 + 2] = r2;
        sRed[qid * 5 + 3] = r3;
    }
    __syncthreads();   // (B) overlay complete; r broadcast
    if (half) {
        r0 = sRed[qid * 5 + 0];
        r1 = sRed[qid * 5 + 1];
        r2 = sRed[qid * 5 + 2];
        r3 = sRed[qid * 5 + 3];
    }
    ull r0p = pk2(r0, r0), r1p = pk2(r1, r1), r2p = pk2(r2, r2), r3p = pk2(r3, r3);

    // ---- FFN: this half's 128 f-pair records ----
    ull o0 = 0ull, o1 = 0ull, o2 = 0ull, o3 = 0ull;
    int tbeg = half * (FREC / 2);
    #pragma unroll 4
    for (int t = tbeg; t < tbeg + FREC / 2; ++t) {
        ulonglong2 wa = sF1[t], wb = sF2[t];
        ull hp = fma2(r0p, wa.x, sFB[t]);
        hp = fma2(r1p, wa.y, hp);
        hp = fma2(r2p, wb.x, hp);
        hp = fma2(r3p, wb.y, hp);
        float2 hh = upk2(hp);
        ull hr = pk2(fmaxf(hh.x, 0.f), fmaxf(hh.y, 0.f));
        ulonglong2 va = sF3[t], vb = sF4[t];
        o0 = fma2(hr, va.x, o0);
        o1 = fma2(hr, va.y, o1);
        o2 = fma2(hr, vb.x, o2);
        o3 = fma2(hr, vb.y, o3);
    }
    float2 t2;
    t2 = upk2(o0); float fo0 = t2.x + t2.y;
    t2 = upk2(o1); float fo1 = t2.x + t2.y;
    t2 = upk2(o2); float fo2 = t2.x + t2.y;
    t2 = upk2(o3); float fo3 = t2.x + t2.y;

    if (half) {
        sRed[qid * 5 + 0] = fo0;
        sRed[qid * 5 + 1] = fo1;
        sRed[qid * 5 + 2] = fo2;
        sRed[qid * 5 + 3] = fo3;
    }
    __syncthreads();   // (C) ffn partials visible
    if (!half) {
        fo0 += sRed[qid * 5 + 0];
        fo1 += sRed[qid * 5 + 1];
        fo2 += sRed[qid * 5 + 2];
        fo3 += sRed[qid * 5 + 3];
        float h2[4];
        h2[0] = r0 + fo0 + b2[LAYER * 4 + 0];
        h2[1] = r1 + fo1 + b2[LAYER * 4 + 1];
        h2[2] = r2 + fo2 + b2[LAYER * 4 + 2];
        h2[3] = r3 + fo3 + b2[LAYER * 4 + 3];
        ln4(h2, g2, be2, LAYER);

        if (LAYER == 0) {
            float4 nx = make_float4(h2[0], h2[1], h2[2], h2[3]);
            d_X[q] = nx;
            d_c[q] = cfeat(sCs[1], nx);
        } else {
            out[q] = fmaf(h2[0], Wfc[0], fmaf(h2[1], Wfc[1],
                     fmaf(h2[2], Wfc[2], fmaf(h2[3], Wfc[3], bfc[0]))));
        }
    }
}

extern "C" void kernel_launch(void* const* d_in, const int* in_sizes, int n_in,
                              void* d_out, int out_size)
{
    const float* KEY   = (const float*)d_in[0];
    const float* VALUE = (const float*)d_in[1];
    const float* Wq    = (const float*)d_in[2];
    const float* bq    = (const float*)d_in[3];
    const float* Wk    = (const float*)d_in[4];
    const float* bk    = (const float*)d_in[5];
    const float* Wv    = (const float*)d_in[6];
    const float* bv    = (const float*)d_in[7];
    const float* Wo    = (const float*)d_in[8];
    const float* bo    = (const float*)d_in[9];
    const float* bw    = (const float*)d_in[10];
    const float* g1    = (const float*)d_in[11];
    const float* be1   = (const float*)d_in[12];
    const float* W1    = (const float*)d_in[13];
    const float* b1    = (const float*)d_in[14];
    const float* W2    = (const float*)d_in[15];
    const float* b2    = (const float*)d_in[16];
    const float* g2    = (const float*)d_in[17];
    const float* be2   = (const float*)d_in[18];
    const float* Wfc   = (const float*)d_in[19];
    const float* bfc   = (const float*)d_in[20];

    k_att<0><<<dim3(32, 16), 128>>>(KEY, VALUE, nullptr,
        Wq, bq, Wk, bk, Wv, bv, Wo, bo, bw,
        g1, be1, W1, b1, W2, b2, g2, be2, Wfc, bfc);
    k_att<1><<<dim3(32, 16), 128>>>(KEY, VALUE, (float*)d_out,
        Wq, bq, Wk, bk, Wv, bv, Wo, bo, bw,
        g1, be1, W1, b1, W2, b2, g2, be2, Wfc, bfc);
}

// round 12
// speedup vs baseline: 1.1441x; 1.1441x over previous
#include <cuda_runtime.h>

typedef unsigned long long ull;

#define NB    16
#define SLEN  2048
#define NTOK  (NB * SLEN)
#define HDIM  256
#define FDIM  512
#define NREC  (SLEN / 2)   // key-pair records
#define FREC  (FDIM / 2)   // ffn-pair records
#define TILE  32           // queries per CTA
#define LOG2E 1.4426950408889634f

struct LayerConsts {
    float A2[16];   // log2e*bw^2 * Wq Wk^T
    float M2[16];   // 0.5*log2e*bw^2 * Wk Wk^T
    float Cm[16];   // Wv Wo
    float cvec[4];  // log2e*bw^2 * (Wk bq - Wk bk)
    float d0[4];    // Wo^T bv + bo
    float cconst;   // log2e*bw^2 * (bq.bk - 0.5|bk|^2)
};
#define LC_FLOATS (int)(sizeof(LayerConsts) * 2 / 4)

__device__ float4 d_X[NTOK];
__device__ float  d_c[NTOK];
__device__ LayerConsts d_cg[2];   // written by k_att<0> CTA(0,0), read by k_att<1>

// ---------------- packed fp32x2 helpers ----------------
__device__ __forceinline__ ull fma2(ull a, ull b, ull c) {
    ull d; asm("fma.rn.f32x2 %0, %1, %2, %3;" : "=l"(d) : "l"(a), "l"(b), "l"(c)); return d;
}
__device__ __forceinline__ ull add2(ull a, ull b) {
    ull d; asm("add.rn.f32x2 %0, %1, %2;" : "=l"(d) : "l"(a), "l"(b)); return d;
}
__device__ __forceinline__ ull pk2(float lo, float hi) {
    ull r; asm("mov.b64 %0, {%1, %2};" : "=l"(r) : "f"(lo), "f"(hi)); return r;
}
__device__ __forceinline__ float2 upk2(ull x) {
    float2 r; asm("mov.b64 {%0, %1}, %2;" : "=f"(r.x), "=f"(r.y) : "l"(x)); return r;
}
__device__ __forceinline__ float fast_exp2(float x) {
    float r; asm("ex2.approx.ftz.f32 %0, %1;" : "=f"(r) : "f"(x)); return r;
}

// per-key logit constant c = cconst + sum_i (cvec_i - (M2 x)_i) x_i
__device__ __forceinline__ float cfeat(const LayerConsts& C, float4 xv)
{
    float x[4] = {xv.x, xv.y, xv.z, xv.w};
    float c = C.cconst;
    #pragma unroll
    for (int i = 0; i < 4; ++i) {
        float mi = 0.f;
        #pragma unroll
        for (int j = 0; j < 4; ++j) mi = fmaf(C.M2[i * 4 + j], x[j], mi);
        c = fmaf(C.cvec[i] - mi, x[i], c);
    }
    return c;
}

__device__ __forceinline__ void ln4(float h[4], const float* __restrict__ g,
                                    const float* __restrict__ be, int l)
{
    float mean = 0.25f * (h[0] + h[1] + h[2] + h[3]);
    float e0 = h[0] - mean, e1 = h[1] - mean, e2 = h[2] - mean, e3 = h[3] - mean;
    float var = 0.25f * (e0 * e0 + e1 * e1 + e2 * e2 + e3 * e3);
    float r = rsqrtf(var + 1e-5f);
    h[0] = fmaf(e0 * r, g[l * 4 + 0], be[l * 4 + 0]);
    h[1] = fmaf(e1 * r, g[l * 4 + 1], be[l * 4 + 1]);
    h[2] = fmaf(e2 * r, g[l * 4 + 2], be[l * 4 + 2]);
    h[3] = fmaf(e3 * r, g[l * 4 + 3], be[l * 4 + 3]);
}

// ---------------------------------------------------------------------------
// Fused attention + LN1 + FFN + LN2 (+ next-layer feat / final fc).
// grid (64, 16), 128 threads: thread = (query qid = tid&31, part = tid>>5).
// TILE=32 queries/CTA doubles the grid to 1024 CTAs -> 5 CTAs/SM resident
// (smem 43KB, regs <=102 via launch_bounds(128,5)) = 20 warps/SM, vs 13.8
// at TILE=64. Each part processes 512 keys (256 pair-records) and 64 FFN
// f-pair records; parts combine through sRed.
// LAYER 0 computes the 4x4 layer constants per-CTA (warp-per-task outer
// products), CTA(0,0) publishes to d_cg; LAYER 1 copies them.
// True logit <= 0 (max exactly 0 on the diagonal); per-query softmax-
// invariant shift cancels in normalization -> no max pass, no overflow.
// ---------------------------------------------------------------------------
#define SMEM_BYTES (NREC * 40)
static_assert(FREC * 16 * 4 + FREC * 8 <= SMEM_BYTES, "ffn overlay exceeds key smem");

template <int LAYER>
__global__ void __launch_bounds__(128, 5)
k_att(const float* __restrict__ KEY, const float* __restrict__ VAL,
      float* __restrict__ out,
      const float* __restrict__ Wq, const float* __restrict__ bq,
      const float* __restrict__ Wk, const float* __restrict__ bk,
      const float* __restrict__ Wv, const float* __restrict__ bv,
      const float* __restrict__ Wo, const float* __restrict__ bo,
      const float* __restrict__ bw,
      const float* __restrict__ g1, const float* __restrict__ be1,
      const float* __restrict__ W1, const float* __restrict__ b1,
      const float* __restrict__ W2, const float* __restrict__ b2,
      const float* __restrict__ g2, const float* __restrict__ be2,
      const float* __restrict__ Wfc, const float* __restrict__ bfc)
{
    __shared__ __align__(16) unsigned char smraw[SMEM_BYTES];   // 40960 B
    __shared__ float sRed[TILE * 5 * 3];   // parts 1..3 partials
    __shared__ float sR[TILE * 4];         // LN1 result broadcast
    __shared__ float sAcc[124];            // raw contraction outputs (2 layers x 62)
    __shared__ LayerConsts sCs[2];

    ulonglong2* sKA = (ulonglong2*)smraw;
    ulonglong2* sKB = (ulonglong2*)(smraw + NREC * 16);
    ull*        sKC = (ull*)(smraw + NREC * 32);
    // FFN overlay (written after attention phase): 18 KB
    ulonglong2* sF1 = (ulonglong2*)smraw;
    ulonglong2* sF2 = sF1 + FREC;
    ulonglong2* sF3 = sF2 + FREC;
    ulonglong2* sF4 = sF3 + FREC;
    ull*        sFB = (ull*)(sF4 + FREC);

    int tid  = threadIdx.x;
    int qid  = tid & (TILE - 1);
    int part = tid >> 5;               // 0..3 (== warp id)
    int w = tid >> 5, lane = tid & 31;
    int base = blockIdx.y * SLEN;
    int q = base + blockIdx.x * TILE + qid;

    if (LAYER == 0) {
        // ---- prologue: layer constants, warp-per-task outer products ----
        #pragma unroll
        for (int pass = 0; pass < 2; ++pass) {
            int t = w + 4 * pass;
            int l = t >> 2, type = t & 3;
            const float* wqp = Wq + l * 4 * HDIM;
            const float* wkp = Wk + l * 4 * HDIM;
            const float* wvp = Wv + l * 4 * HDIM;
            const float* wop = Wo + l * HDIM * 4;
            const float* bqp = bq + l * HDIM;
            const float* bkp = bk + l * HDIM;
            const float* bvp = bv + l * HDIM;

            float av[16];
            #pragma unroll
            for (int i = 0; i < 16; ++i) av[i] = 0.f;

            if (type == 0) {
                #pragma unroll
                for (int c = 0; c < 8; ++c) {
                    int h = lane + 32 * c;
                    float a[4], b[4];
                    #pragma unroll
                    for (int i = 0; i < 4; ++i) { a[i] = wqp[i * HDIM + h]; b[i] = wkp[i * HDIM + h]; }
                    #pragma unroll
                    for (int i = 0; i < 4; ++i)
                        #pragma unroll
                        for (int j = 0; j < 4; ++j) av[i * 4 + j] = fmaf(a[i], b[j], av[i * 4 + j]);
                }
            } else if (type == 1) {
                #pragma unroll
                for (int c = 0; c < 8; ++c) {
                    int h = lane + 32 * c;
                    float b[4];
                    #pragma unroll
                    for (int i = 0; i < 4; ++i) b[i] = wkp[i * HDIM + h];
                    #pragma unroll
                    for (int i = 0; i < 4; ++i)
                        #pragma unroll
                        for (int j = 0; j < 4; ++j) av[i * 4 + j] = fmaf(b[i], b[j], av[i * 4 + j]);
                }
            } else if (type == 2) {
                #pragma unroll
                for (int c = 0; c < 8; ++c) {
                    int h = lane + 32 * c;
                    float a[4], b[4];
                    #pragma unroll
                    for (int i = 0; i < 4; ++i) { a[i] = wvp[i * HDIM + h]; b[i] = wop[h * 4 + i]; }
                    #pragma unroll
                    for (int i = 0; i < 4; ++i)
                        #pragma unroll
                        for (int j = 0; j < 4; ++j) av[i * 4 + j] = fmaf(a[i], b[j], av[i * 4 + j]);
                }
            } else {
                #pragma unroll
                for (int c = 0; c < 8; ++c) {
                    int h = lane + 32 * c;
                    float kvv[4], ov[4];
                    #pragma unroll
                    for (int i = 0; i < 4; ++i) { kvv[i] = wkp[i * HDIM + h]; ov[i] = wop[h * 4 + i]; }
                    float bqv = bqp[h], bkv = bkp[h], bvv = bvp[h];
                    #pragma unroll
                    for (int i = 0; i < 4; ++i) {
                        av[i]     = fmaf(kvv[i], bqv, av[i]);
                        av[4 + i] = fmaf(kvv[i], bkv, av[4 + i]);
                        av[8 + i] = fmaf(bvv, ov[i], av[8 + i]);
                    }
                    av[12] = fmaf(bqv, bkv, av[12]);
                    av[13] = fmaf(bkv, bkv, av[13]);
                }
            }

            #pragma unroll
            for (int i = 0; i < 16; ++i) {
                float s = av[i];
                s += __shfl_xor_sync(0xffffffffu, s, 16);
                s += __shfl_xor_sync(0xffffffffu, s, 8);
                s += __shfl_xor_sync(0xffffffffu, s, 4);
                s += __shfl_xor_sync(0xffffffffu, s, 2);
                s += __shfl_xor_sync(0xffffffffu, s, 1);
                av[i] = s;
            }
            if (lane == 0) {
                int nout = (type == 3) ? 14 : 16;
                int obase = 62 * l + type * 16;   // type 3 -> 48
                #pragma unroll
                for (int i = 0; i < 16; ++i)
                    if (i < nout) sAcc[obase + i] = av[i];
            }
        }
        __syncthreads();
        if (tid < 64) {
            int l = tid >> 5, sub = tid & 31;
            const float* accL = sAcc + 62 * l;
            float sc = LOG2E * bw[l] * bw[l];
            LayerConsts* C = &sCs[l];
            if (sub < 16) {
                C->A2[sub] = sc * accL[sub];
                C->M2[sub] = 0.5f * sc * accL[16 + sub];
                C->Cm[sub] = accL[32 + sub];
            } else if (sub < 20) {
                int i = sub - 16;
                C->cvec[i] = sc * (accL[48 + i] - accL[52 + i]);
                C->d0[i]   = accL[56 + i] + bo[l * 4 + i];
            } else if (sub == 20) {
                C->cconst = sc * (accL[60] - 0.5f * accL[61]);
            }
        }
        __syncthreads();
        if (blockIdx.x == 0 && blockIdx.y == 0 && tid < LC_FLOATS)
            ((float*)d_cg)[tid] = ((const float*)sCs)[tid];
    } else {
        if (tid < LC_FLOATS)
            ((float*)sCs)[tid] = ((const float*)d_cg)[tid];
        __syncthreads();
    }

    const LayerConsts& Cs = sCs[LAYER];

    // ---- prefill key pairs (all 128 threads) ----
    for (int r = tid; r < NREC; r += 128) {
        int t0 = base + 2 * r;
        float4 x0, x1; float c0, c1;
        if (LAYER == 0) {
            x0 = make_float4(KEY[3 * t0], KEY[3 * t0 + 1], KEY[3 * t0 + 2], VAL[t0]);
            x1 = make_float4(KEY[3 * t0 + 3], KEY[3 * t0 + 4], KEY[3 * t0 + 5], VAL[t0 + 1]);
            c0 = cfeat(Cs, x0);
            c1 = cfeat(Cs, x1);
        } else {
            x0 = d_X[t0]; x1 = d_X[t0 + 1];
            c0 = d_c[t0]; c1 = d_c[t0 + 1];
        }
        sKA[r] = make_ulonglong2(pk2(x0.x, x1.x), pk2(x0.y, x1.y));
        sKB[r] = make_ulonglong2(pk2(x0.z, x1.z), pk2(x0.w, x1.w));
        sKC[r] = pk2(c0, c1);
    }

    float4 xq;
    if (LAYER == 0)
        xq = make_float4(KEY[3 * q], KEY[3 * q + 1], KEY[3 * q + 2], VAL[q]);
    else
        xq = d_X[q];

    // query-folded logit vector gq = A2^T xq, splatted into f32x2 pairs
    float gq0 = xq.x * Cs.A2[0] + xq.y * Cs.A2[4] + xq.z * Cs.A2[8]  + xq.w * Cs.A2[12];
    float gq1 = xq.x * Cs.A2[1] + xq.y * Cs.A2[5] + xq.z * Cs.A2[9]  + xq.w * Cs.A2[13];
    float gq2 = xq.x * Cs.A2[2] + xq.y * Cs.A2[6] + xq.z * Cs.A2[10] + xq.w * Cs.A2[14];
    float gq3 = xq.x * Cs.A2[3] + xq.y * Cs.A2[7] + xq.z * Cs.A2[11] + xq.w * Cs.A2[15];
    ull gx = pk2(gq0, gq0), gy = pk2(gq1, gq1), gz = pk2(gq2, gq2), gw = pk2(gq3, gq3);

    __syncthreads();

    // ---- attention: this part's 256 pair-records ----
    ull sp = 0ull, a0 = 0ull, a1 = 0ull, a2 = 0ull, a3 = 0ull;
    int rbeg = part * (NREC / 4);
    #pragma unroll 8
    for (int r = rbeg; r < rbeg + NREC / 4; ++r) {
        ulonglong2 A = sKA[r];
        ulonglong2 B = sKB[r];
        ull lg = fma2(gx, A.x, sKC[r]);
        lg = fma2(gy, A.y, lg);
        lg = fma2(gz, B.x, lg);
        lg = fma2(gw, B.y, lg);
        float2 lf = upk2(lg);
        ull pp = pk2(fast_exp2(lf.x), fast_exp2(lf.y));
        sp = add2(sp, pp);
        a0 = fma2(pp, A.x, a0);
        a1 = fma2(pp, A.y, a1);
        a2 = fma2(pp, B.x, a2);
        a3 = fma2(pp, B.y, a3);
    }

    // horizontal sums -> 5 scalars
    float2 t2;
    t2 = upk2(sp); float ps  = t2.x + t2.y;
    t2 = upk2(a0); float pa0 = t2.x + t2.y;
    t2 = upk2(a1); float pa1 = t2.x + t2.y;
    t2 = upk2(a2); float pa2 = t2.x + t2.y;
    t2 = upk2(a3); float pa3 = t2.x + t2.y;

    if (part) {
        float* dst = sRed + (part - 1) * (TILE * 5) + qid * 5;
        dst[0] = ps; dst[1] = pa0; dst[2] = pa1; dst[3] = pa2; dst[4] = pa3;
    }
    __syncthreads();   // (A) attn done; partials visible; key smem dead

    // FFN weight overlay straight from global: 2 records per thread
    for (int i = tid; i < FREC; i += 128) {
        int f = 2 * i;
        const float* w1 = W1 + LAYER * 4 * FDIM;
        const float* w2 = W2 + LAYER * FDIM * 4;
        float2 u0 = *(const float2*)(w1 + 0 * FDIM + f);
        float2 u1 = *(const float2*)(w1 + 1 * FDIM + f);
        float2 u2 = *(const float2*)(w1 + 2 * FDIM + f);
        float2 u3 = *(const float2*)(w1 + 3 * FDIM + f);
        float2 bb = *(const float2*)(b1 + LAYER * FDIM + f);
        float4 r0v = *(const float4*)(w2 + f * 4);
        float4 r1v = *(const float4*)(w2 + (f + 1) * 4);
        sF1[i] = make_ulonglong2(pk2(u0.x, u0.y), pk2(u1.x, u1.y));
        sF2[i] = make_ulonglong2(pk2(u2.x, u2.y), pk2(u3.x, u3.y));
        sFB[i] = pk2(bb.x, bb.y);
        sF3[i] = make_ulonglong2(pk2(r0v.x, r1v.x), pk2(r0v.y, r1v.y));
        sF4[i] = make_ulonglong2(pk2(r0v.z, r1v.z), pk2(r0v.w, r1v.w));
    }

    float r0, r1, r2, r3;
    if (!part) {
        #pragma unroll
        for (int pp2 = 0; pp2 < 3; ++pp2) {
            const float* src = sRed + pp2 * (TILE * 5) + qid * 5;
            ps  += src[0]; pa0 += src[1]; pa1 += src[2]; pa2 += src[3]; pa3 += src[4];
        }
        float inv = 1.0f / ps;
        float h[4];
        #pragma unroll
        for (int j = 0; j < 4; ++j) {
            float vj = pa0 * Cs.Cm[0 * 4 + j] + pa1 * Cs.Cm[1 * 4 + j]
                     + pa2 * Cs.Cm[2 * 4 + j] + pa3 * Cs.Cm[3 * 4 + j];
            h[j] = ((&xq.x)[j]) + fmaf(vj, inv, Cs.d0[j]);
        }
        ln4(h, g1, be1, LAYER);
        r0 = h[0]; r1 = h[1]; r2 = h[2]; r3 = h[3];
        sR[qid * 4 + 0] = r0;
        sR[qid * 4 + 1] = r1;
        sR[qid * 4 + 2] = r2;
        sR[qid * 4 + 3] = r3;
    }
    __syncthreads();   // (B) overlay complete; r broadcast
    if (part) {
        r0 = sR[qid * 4 + 0];
        r1 = sR[qid * 4 + 1];
        r2 = sR[qid * 4 + 2];
        r3 = sR[qid * 4 + 3];
    }
    ull r0p = pk2(r0, r0), r1p = pk2(r1, r1), r2p = pk2(r2, r2), r3p = pk2(r3, r3);

    // ---- FFN: this part's 64 f-pair records ----
    ull o0 = 0ull, o1 = 0ull, o2 = 0ull, o3 = 0ull;
    int tbeg = part * (FREC / 4);
    #pragma unroll 4
    for (int t = tbeg; t < tbeg + FREC / 4; ++t) {
        ulonglong2 wa = sF1[t], wb = sF2[t];
        ull hp = fma2(r0p, wa.x, sFB[t]);
        hp = fma2(r1p, wa.y, hp);
        hp = fma2(r2p, wb.x, hp);
        hp = fma2(r3p, wb.y, hp);
        float2 hh = upk2(hp);
        ull hr = pk2(fmaxf(hh.x, 0.f), fmaxf(hh.y, 0.f));
        ulonglong2 va = sF3[t], vb = sF4[t];
        o0 = fma2(hr, va.x, o0);
        o1 = fma2(hr, va.y, o1);
        o2 = fma2(hr, vb.x, o2);
        o3 = fma2(hr, vb.y, o3);
    }
    t2 = upk2(o0); float fo0 = t2.x + t2.y;
    t2 = upk2(o1); float fo1 = t2.x + t2.y;
    t2 = upk2(o2); float fo2 = t2.x + t2.y;
    t2 = upk2(o3); float fo3 = t2.x + t2.y;

    if (part) {
        float* dst = sRed + (part - 1) * (TILE * 5) + qid * 5;
        dst[0] = fo0; dst[1] = fo1; dst[2] = fo2; dst[3] = fo3;
    }
    __syncthreads();   // (C) ffn partials visible
    if (!part) {
        #pragma unroll
        for (int pp2 = 0; pp2 < 3; ++pp2) {
            const float* src = sRed + pp2 * (TILE * 5) + qid * 5;
            fo0 += src[0]; fo1 += src[1]; fo2 += src[2]; fo3 += src[3];
        }
        float h2[4];
        h2[0] = r0 + fo0 + b2[LAYER * 4 + 0];
        h2[1] = r1 + fo1 + b2[LAYER * 4 + 1];
        h2[2] = r2 + fo2 + b2[LAYER * 4 + 2];
        h2[3] = r3 + fo3 + b2[LAYER * 4 + 3];
        ln4(h2, g2, be2, LAYER);

        if (LAYER == 0) {
            float4 nx = make_float4(h2[0], h2[1], h2[2], h2[3]);
            d_X[q] = nx;
            d_c[q] = cfeat(sCs[1], nx);
        } else {
            out[q] = fmaf(h2[0], Wfc[0], fmaf(h2[1], Wfc[1],
                     fmaf(h2[2], Wfc[2], fmaf(h2[3], Wfc[3], bfc[0]))));
        }
    }
}

extern "C" void kernel_launch(void* const* d_in, const int* in_sizes, int n_in,
                              void* d_out, int out_size)
{
    const float* KEY   = (const float*)d_in[0];
    const float* VALUE = (const float*)d_in[1];
    const float* Wq    = (const float*)d_in[2];
    const float* bq    = (const float*)d_in[3];
    const float* Wk    = (const float*)d_in[4];
    const float* bk    = (const float*)d_in[5];
    const float* Wv    = (const float*)d_in[6];
    const float* bv    = (const float*)d_in[7];
    const float* Wo    = (const float*)d_in[8];
    const float* bo    = (const float*)d_in[9];
    const float* bw    = (const float*)d_in[10];
    const float* g1    = (const float*)d_in[11];
    const float* be1   = (const float*)d_in[12];
    const float* W1    = (const float*)d_in[13];
    const float* b1    = (const float*)d_in[14];
    const float* W2    = (const float*)d_in[15];
    const float* b2    = (const float*)d_in[16];
    const float* g2    = (const float*)d_in[17];
    const float* be2   = (const float*)d_in[18];
    const float* Wfc   = (const float*)d_in[19];
    const float* bfc   = (const float*)d_in[20];

    k_att<0><<<dim3(SLEN / TILE, NB), 128>>>(KEY, VALUE, nullptr,
        Wq, bq, Wk, bk, Wv, bv, Wo, bo, bw,
        g1, be1, W1, b1, W2, b2, g2, be2, Wfc, bfc);
    k_att<1><<<dim3(SLEN / TILE, NB), 128>>>(KEY, VALUE, (float*)d_out,
        Wq, bq, Wk, bk, Wv, bv, Wo, bo, bw,
        g1, be1, W1, b1, W2, b2, g2, be2, Wfc, bfc);
}

// round 13
// speedup vs baseline: 1.1992x; 1.0482x over previous
#include <cuda_runtime.h>

typedef unsigned long long ull;

#define NB    16
#define SLEN  2048
#define NTOK  (NB * SLEN)
#define HDIM  256
#define FDIM  512
#define NREC  (SLEN / 2)   // key-pair records
#define FREC  (FDIM / 2)   // ffn-pair records
#define TILE  32           // queries per CTA
#define NPART 8            // key partitions (one per thread group)
#define RPT   (NREC / NPART)   // 128 records per thread
#define LOG2E 1.4426950408889634f

struct LayerConsts {
    float A2[16];   // log2e*bw^2 * Wq Wk^T
    float M2[16];   // 0.5*log2e*bw^2 * Wk Wk^T
    float Cm[16];   // Wv Wo
    float cvec[4];  // log2e*bw^2 * (Wk bq - Wk bk)
    float d0[4];    // Wo^T bv + bo
    float cconst;   // log2e*bw^2 * (bq.bk - 0.5|bk|^2)
};
#define LC_FLOATS (int)(sizeof(LayerConsts) * 2 / 4)

__device__ float4 d_X[NTOK];
__device__ float  d_c[NTOK];
__device__ LayerConsts d_cg[2];   // written by k_att<0> CTA(0,0), read by k_att<1>

// ---------------- packed fp32x2 helpers ----------------
__device__ __forceinline__ ull fma2(ull a, ull b, ull c) {
    ull d; asm("fma.rn.f32x2 %0, %1, %2, %3;" : "=l"(d) : "l"(a), "l"(b), "l"(c)); return d;
}
__device__ __forceinline__ ull add2(ull a, ull b) {
    ull d; asm("add.rn.f32x2 %0, %1, %2;" : "=l"(d) : "l"(a), "l"(b)); return d;
}
__device__ __forceinline__ ull pk2(float lo, float hi) {
    ull r; asm("mov.b64 %0, {%1, %2};" : "=l"(r) : "f"(lo), "f"(hi)); return r;
}
__device__ __forceinline__ float2 upk2(ull x) {
    float2 r; asm("mov.b64 {%0, %1}, %2;" : "=f"(r.x), "=f"(r.y) : "l"(x)); return r;
}
__device__ __forceinline__ float hsum2(ull x) {
    float2 t = upk2(x); return t.x + t.y;
}
__device__ __forceinline__ float fast_exp2(float x) {
    float r; asm("ex2.approx.ftz.f32 %0, %1;" : "=f"(r) : "f"(x)); return r;
}

// per-key logit constant c = cconst + sum_i (cvec_i - (M2 x)_i) x_i
__device__ __forceinline__ float cfeat(const LayerConsts& C, float4 xv)
{
    float x[4] = {xv.x, xv.y, xv.z, xv.w};
    float c = C.cconst;
    #pragma unroll
    for (int i = 0; i < 4; ++i) {
        float mi = 0.f;
        #pragma unroll
        for (int j = 0; j < 4; ++j) mi = fmaf(C.M2[i * 4 + j], x[j], mi);
        c = fmaf(C.cvec[i] - mi, x[i], c);
    }
    return c;
}

__device__ __forceinline__ void ln4(float h[4], const float* __restrict__ g,
                                    const float* __restrict__ be, int l)
{
    float mean = 0.25f * (h[0] + h[1] + h[2] + h[3]);
    float e0 = h[0] - mean, e1 = h[1] - mean, e2 = h[2] - mean, e3 = h[3] - mean;
    float var = 0.25f * (e0 * e0 + e1 * e1 + e2 * e2 + e3 * e3);
    float r = rsqrtf(var + 1e-5f);
    h[0] = fmaf(e0 * r, g[l * 4 + 0], be[l * 4 + 0]);
    h[1] = fmaf(e1 * r, g[l * 4 + 1], be[l * 4 + 1]);
    h[2] = fmaf(e2 * r, g[l * 4 + 2], be[l * 4 + 2]);
    h[3] = fmaf(e3 * r, g[l * 4 + 3], be[l * 4 + 3]);
}

// ---------------------------------------------------------------------------
// Fused attention + LN1 + FFN + LN2 (+ next-layer feat / final fc).
// grid (64, 16), 128 threads, TILE=32 queries/CTA.
// ATTENTION: thread = (qslot = tid&15, part = tid>>4). Each thread owns TWO
// queries (2*qslot, 2*qslot+1) and 128 records [part*128, ...): one record
// load (3 LDS) now feeds FOUR query-key pairs -> half the smem crossbar
// traffic of R12 (L1 was 69.6%, the top pipe) and two independent logit
// chains per thread for ILP.
// Reduction buffers (pRed, sR) overlay dead key smem after the attn loop,
// keeping static smem ~42KB so 5 CTAs/SM remain possible if regs allow.
// FFN: thread = (qid = tid&31, fpart = tid>>5), 64 f-pair records each.
// LAYER 0 computes layer constants per-CTA; CTA(0,0) publishes to d_cg;
// LAYER 1 copies them.
// True logit <= 0 (max exactly 0 on the diagonal); per-query softmax-
// invariant shift cancels in normalization -> no max pass, no overflow.
// ---------------------------------------------------------------------------
#define SMEM_BYTES (NREC * 40)
static_assert(FREC * 16 * 4 + FREC * 8 <= SMEM_BYTES, "ffn overlay exceeds key smem");
// pRed overlay: [20480, 20480 + 7*TILE*5*4) = [20480, 24960) inside dead sKB
// sR overlay:   [25600, 25600 + TILE*4*4)   = [25600, 26112)
static_assert(20480 + 7 * TILE * 5 * 4 <= 25600, "pRed/sR overlap");
static_assert(25600 + TILE * 4 * 4 <= SMEM_BYTES, "sR exceeds key smem");
static_assert(FREC * 16 * 4 + FREC * 8 <= 20480, "ffn overlay hits pRed");

template <int LAYER>
__global__ void __launch_bounds__(128, 4)
k_att(const float* __restrict__ KEY, const float* __restrict__ VAL,
      float* __restrict__ out,
      const float* __restrict__ Wq, const float* __restrict__ bq,
      const float* __restrict__ Wk, const float* __restrict__ bk,
      const float* __restrict__ Wv, const float* __restrict__ bv,
      const float* __restrict__ Wo, const float* __restrict__ bo,
      const float* __restrict__ bw,
      const float* __restrict__ g1, const float* __restrict__ be1,
      const float* __restrict__ W1, const float* __restrict__ b1,
      const float* __restrict__ W2, const float* __restrict__ b2,
      const float* __restrict__ g2, const float* __restrict__ be2,
      const float* __restrict__ Wfc, const float* __restrict__ bfc)
{
    __shared__ __align__(16) unsigned char smraw[SMEM_BYTES];   // 40960 B
    __shared__ float sAcc[124];        // raw contraction outputs (2 layers x 62)
    __shared__ LayerConsts sCs[2];

    ulonglong2* sKA = (ulonglong2*)smraw;
    ulonglong2* sKB = (ulonglong2*)(smraw + NREC * 16);
    ull*        sKC = (ull*)(smraw + NREC * 32);
    // FFN overlay (valid after sync A): 18 KB at offset 0
    ulonglong2* sF1 = (ulonglong2*)smraw;
    ulonglong2* sF2 = sF1 + FREC;
    ulonglong2* sF3 = sF2 + FREC;
    ulonglong2* sF4 = sF3 + FREC;
    ull*        sFB = (ull*)(sF4 + FREC);
    // reduction overlays (valid after sync A)
    float* pRed = (float*)(smraw + 20480);   // 7 parts x TILE x 5 (attn) / 3 x TILE x 5 (ffn)
    float* sR   = (float*)(smraw + 25600);   // TILE x 4 (LN1 broadcast)

    int tid   = threadIdx.x;
    int qslot = tid & 15;
    int part  = tid >> 4;              // 0..7
    int w = tid >> 5, lane = tid & 31;
    int base = blockIdx.y * SLEN;
    int tile0 = blockIdx.x * TILE;

    if (LAYER == 0) {
        // ---- prologue: layer constants, warp-per-task outer products ----
        #pragma unroll
        for (int pass = 0; pass < 2; ++pass) {
            int t = w + 4 * pass;
            int l = t >> 2, type = t & 3;
            const float* wqp = Wq + l * 4 * HDIM;
            const float* wkp = Wk + l * 4 * HDIM;
            const float* wvp = Wv + l * 4 * HDIM;
            const float* wop = Wo + l * HDIM * 4;
            const float* bqp = bq + l * HDIM;
            const float* bkp = bk + l * HDIM;
            const float* bvp = bv + l * HDIM;

            float av[16];
            #pragma unroll
            for (int i = 0; i < 16; ++i) av[i] = 0.f;

            if (type == 0) {
                #pragma unroll
                for (int c = 0; c < 8; ++c) {
                    int h = lane + 32 * c;
                    float a[4], b[4];
                    #pragma unroll
                    for (int i = 0; i < 4; ++i) { a[i] = wqp[i * HDIM + h]; b[i] = wkp[i * HDIM + h]; }
                    #pragma unroll
                    for (int i = 0; i < 4; ++i)
                        #pragma unroll
                        for (int j = 0; j < 4; ++j) av[i * 4 + j] = fmaf(a[i], b[j], av[i * 4 + j]);
                }
            } else if (type == 1) {
                #pragma unroll
                for (int c = 0; c < 8; ++c) {
                    int h = lane + 32 * c;
                    float b[4];
                    #pragma unroll
                    for (int i = 0; i < 4; ++i) b[i] = wkp[i * HDIM + h];
                    #pragma unroll
                    for (int i = 0; i < 4; ++i)
                        #pragma unroll
                        for (int j = 0; j < 4; ++j) av[i * 4 + j] = fmaf(b[i], b[j], av[i * 4 + j]);
                }
            } else if (type == 2) {
                #pragma unroll
                for (int c = 0; c < 8; ++c) {
                    int h = lane + 32 * c;
                    float a[4], b[4];
                    #pragma unroll
                    for (int i = 0; i < 4; ++i) { a[i] = wvp[i * HDIM + h]; b[i] = wop[h * 4 + i]; }
                    #pragma unroll
                    for (int i = 0; i < 4; ++i)
                        #pragma unroll
                        for (int j = 0; j < 4; ++j) av[i * 4 + j] = fmaf(a[i], b[j], av[i * 4 + j]);
                }
            } else {
                #pragma unroll
                for (int c = 0; c < 8; ++c) {
                    int h = lane + 32 * c;
                    float kvv[4], ov[4];
                    #pragma unroll
                    for (int i = 0; i < 4; ++i) { kvv[i] = wkp[i * HDIM + h]; ov[i] = wop[h * 4 + i]; }
                    float bqv = bqp[h], bkv = bkp[h], bvv = bvp[h];
                    #pragma unroll
                    for (int i = 0; i < 4; ++i) {
                        av[i]     = fmaf(kvv[i], bqv, av[i]);
                        av[4 + i] = fmaf(kvv[i], bkv, av[4 + i]);
                        av[8 + i] = fmaf(bvv, ov[i], av[8 + i]);
                    }
                    av[12] = fmaf(bqv, bkv, av[12]);
                    av[13] = fmaf(bkv, bkv, av[13]);
                }
            }

            #pragma unroll
            for (int i = 0; i < 16; ++i) {
                float s = av[i];
                s += __shfl_xor_sync(0xffffffffu, s, 16);
                s += __shfl_xor_sync(0xffffffffu, s, 8);
                s += __shfl_xor_sync(0xffffffffu, s, 4);
                s += __shfl_xor_sync(0xffffffffu, s, 2);
                s += __shfl_xor_sync(0xffffffffu, s, 1);
                av[i] = s;
            }
            if (lane == 0) {
                int nout = (type == 3) ? 14 : 16;
                int obase = 62 * l + type * 16;   // type 3 -> 48
                #pragma unroll
                for (int i = 0; i < 16; ++i)
                    if (i < nout) sAcc[obase + i] = av[i];
            }
        }
        __syncthreads();
        if (tid < 64) {
            int l = tid >> 5, sub = tid & 31;
            const float* accL = sAcc + 62 * l;
            float sc = LOG2E * bw[l] * bw[l];
            LayerConsts* C = &sCs[l];
            if (sub < 16) {
                C->A2[sub] = sc * accL[sub];
                C->M2[sub] = 0.5f * sc * accL[16 + sub];
                C->Cm[sub] = accL[32 + sub];
            } else if (sub < 20) {
                int i = sub - 16;
                C->cvec[i] = sc * (accL[48 + i] - accL[52 + i]);
                C->d0[i]   = accL[56 + i] + bo[l * 4 + i];
            } else if (sub == 20) {
                C->cconst = sc * (accL[60] - 0.5f * accL[61]);
            }
        }
        __syncthreads();
        if (blockIdx.x == 0 && blockIdx.y == 0 && tid < LC_FLOATS)
            ((float*)d_cg)[tid] = ((const float*)sCs)[tid];
    } else {
        if (tid < LC_FLOATS)
            ((float*)sCs)[tid] = ((const float*)d_cg)[tid];
        __syncthreads();
    }

    const LayerConsts& Cs = sCs[LAYER];

    // ---- prefill key pairs (all 128 threads) ----
    for (int r = tid; r < NREC; r += 128) {
        int t0 = base + 2 * r;
        float4 x0, x1; float c0, c1;
        if (LAYER == 0) {
            x0 = make_float4(KEY[3 * t0], KEY[3 * t0 + 1], KEY[3 * t0 + 2], VAL[t0]);
            x1 = make_float4(KEY[3 * t0 + 3], KEY[3 * t0 + 4], KEY[3 * t0 + 5], VAL[t0 + 1]);
            c0 = cfeat(Cs, x0);
            c1 = cfeat(Cs, x1);
        } else {
            x0 = d_X[t0]; x1 = d_X[t0 + 1];
            c0 = d_c[t0]; c1 = d_c[t0 + 1];
        }
        sKA[r] = make_ulonglong2(pk2(x0.x, x1.x), pk2(x0.y, x1.y));
        sKB[r] = make_ulonglong2(pk2(x0.z, x1.z), pk2(x0.w, x1.w));
        sKC[r] = pk2(c0, c1);
    }

    // two queries per thread
    int q0g = base + tile0 + 2 * qslot;
    float4 xq0, xq1;
    if (LAYER == 0) {
        xq0 = make_float4(KEY[3 * q0g], KEY[3 * q0g + 1], KEY[3 * q0g + 2], VAL[q0g]);
        xq1 = make_float4(KEY[3 * q0g + 3], KEY[3 * q0g + 4], KEY[3 * q0g + 5], VAL[q0g + 1]);
    } else {
        xq0 = d_X[q0g];
        xq1 = d_X[q0g + 1];
    }

    ull g0[4], g1v[4];
    {
        float a0 = xq0.x * Cs.A2[0] + xq0.y * Cs.A2[4] + xq0.z * Cs.A2[8]  + xq0.w * Cs.A2[12];
        float a1 = xq0.x * Cs.A2[1] + xq0.y * Cs.A2[5] + xq0.z * Cs.A2[9]  + xq0.w * Cs.A2[13];
        float a2 = xq0.x * Cs.A2[2] + xq0.y * Cs.A2[6] + xq0.z * Cs.A2[10] + xq0.w * Cs.A2[14];
        float a3 = xq0.x * Cs.A2[3] + xq0.y * Cs.A2[7] + xq0.z * Cs.A2[11] + xq0.w * Cs.A2[15];
        g0[0] = pk2(a0, a0); g0[1] = pk2(a1, a1); g0[2] = pk2(a2, a2); g0[3] = pk2(a3, a3);
        float b0v = xq1.x * Cs.A2[0] + xq1.y * Cs.A2[4] + xq1.z * Cs.A2[8]  + xq1.w * Cs.A2[12];
        float b1v = xq1.x * Cs.A2[1] + xq1.y * Cs.A2[5] + xq1.z * Cs.A2[9]  + xq1.w * Cs.A2[13];
        float b2v = xq1.x * Cs.A2[2] + xq1.y * Cs.A2[6] + xq1.z * Cs.A2[10] + xq1.w * Cs.A2[14];
        float b3v = xq1.x * Cs.A2[3] + xq1.y * Cs.A2[7] + xq1.z * Cs.A2[11] + xq1.w * Cs.A2[15];
        g1v[0] = pk2(b0v, b0v); g1v[1] = pk2(b1v, b1v); g1v[2] = pk2(b2v, b2v); g1v[3] = pk2(b3v, b3v);
    }

    __syncthreads();

    // ---- attention: 128 records, 2 queries per thread ----
    ull ac0[5], ac1[5];
    #pragma unroll
    for (int k = 0; k < 5; ++k) { ac0[k] = 0ull; ac1[k] = 0ull; }
    int rbeg = part * RPT;
    #pragma unroll 4
    for (int r = rbeg; r < rbeg + RPT; ++r) {
        ulonglong2 A = sKA[r];
        ulonglong2 B = sKB[r];
        ull Cc = sKC[r];

        ull lg0 = fma2(g0[0], A.x, Cc);
        ull lg1 = fma2(g1v[0], A.x, Cc);
        lg0 = fma2(g0[1], A.y, lg0);
        lg1 = fma2(g1v[1], A.y, lg1);
        lg0 = fma2(g0[2], B.x, lg0);
        lg1 = fma2(g1v[2], B.x, lg1);
        lg0 = fma2(g0[3], B.y, lg0);
        lg1 = fma2(g1v[3], B.y, lg1);

        float2 l0 = upk2(lg0);
        float2 l1 = upk2(lg1);
        ull p0 = pk2(fast_exp2(l0.x), fast_exp2(l0.y));
        ull p1 = pk2(fast_exp2(l1.x), fast_exp2(l1.y));

        ac0[0] = add2(ac0[0], p0);
        ac1[0] = add2(ac1[0], p1);
        ac0[1] = fma2(p0, A.x, ac0[1]);
        ac1[1] = fma2(p1, A.x, ac1[1]);
        ac0[2] = fma2(p0, A.y, ac0[2]);
        ac1[2] = fma2(p1, A.y, ac1[2]);
        ac0[3] = fma2(p0, B.x, ac0[3]);
        ac1[3] = fma2(p1, B.x, ac1[3]);
        ac0[4] = fma2(p0, B.y, ac0[4]);
        ac1[4] = fma2(p1, B.y, ac1[4]);
    }

    float P0[5], P1[5];
    #pragma unroll
    for (int k = 0; k < 5; ++k) { P0[k] = hsum2(ac0[k]); P1[k] = hsum2(ac1[k]); }

    __syncthreads();   // (A) all key reads done; key smem dead -> overlays valid

    if (part) {
        float* dst = pRed + (part - 1) * (TILE * 5) + (2 * qslot) * 5;
        #pragma unroll
        for (int k = 0; k < 5; ++k) { dst[k] = P0[k]; dst[5 + k] = P1[k]; }
    }
    // FFN weight overlay straight from global: 2 records per thread
    for (int i = tid; i < FREC; i += 128) {
        int f = 2 * i;
        const float* w1 = W1 + LAYER * 4 * FDIM;
        const float* w2 = W2 + LAYER * FDIM * 4;
        float2 u0 = *(const float2*)(w1 + 0 * FDIM + f);
        float2 u1 = *(const float2*)(w1 + 1 * FDIM + f);
        float2 u2 = *(const float2*)(w1 + 2 * FDIM + f);
        float2 u3 = *(const float2*)(w1 + 3 * FDIM + f);
        float2 bb = *(const float2*)(b1 + LAYER * FDIM + f);
        float4 r0v = *(const float4*)(w2 + f * 4);
        float4 r1v = *(const float4*)(w2 + (f + 1) * 4);
        sF1[i] = make_ulonglong2(pk2(u0.x, u0.y), pk2(u1.x, u1.y));
        sF2[i] = make_ulonglong2(pk2(u2.x, u2.y), pk2(u3.x, u3.y));
        sFB[i] = pk2(bb.x, bb.y);
        sF3[i] = make_ulonglong2(pk2(r0v.x, r1v.x), pk2(r0v.y, r1v.y));
        sF4[i] = make_ulonglong2(pk2(r0v.z, r1v.z), pk2(r0v.w, r1v.w));
    }
    __syncthreads();   // (B) partials + overlay visible

    if (part == 0) {
        #pragma unroll
        for (int j = 0; j < 2; ++j) {
            float ps  = j ? P1[0] : P0[0];
            float pa0 = j ? P1[1] : P0[1];
            float pa1 = j ? P1[2] : P0[2];
            float pa2 = j ? P1[3] : P0[3];
            float pa3 = j ? P1[4] : P0[4];
            #pragma unroll
            for (int p = 0; p < 7; ++p) {
                const float* src = pRed + p * (TILE * 5) + (2 * qslot + j) * 5;
                ps += src[0]; pa0 += src[1]; pa1 += src[2]; pa2 += src[3]; pa3 += src[4];
            }
            float4 xq = j ? xq1 : xq0;
            float inv = 1.0f / ps;
            float h[4];
            #pragma unroll
            for (int jj = 0; jj < 4; ++jj) {
                float vj = pa0 * Cs.Cm[0 * 4 + jj] + pa1 * Cs.Cm[1 * 4 + jj]
                         + pa2 * Cs.Cm[2 * 4 + jj] + pa3 * Cs.Cm[3 * 4 + jj];
                h[jj] = ((&xq.x)[jj]) + fmaf(vj, inv, Cs.d0[jj]);
            }
            ln4(h, g1, be1, LAYER);
            float* dst = sR + (2 * qslot + j) * 4;
            dst[0] = h[0]; dst[1] = h[1]; dst[2] = h[2]; dst[3] = h[3];
        }
    }
    __syncthreads();   // (C) LN1 results broadcast

    // ---- FFN: thread = (qid = tid&31, fpart = tid>>5), 64 f-pairs each ----
    int qid = tid & 31;
    int fpart = tid >> 5;
    float r0 = sR[qid * 4 + 0], r1 = sR[qid * 4 + 1];
    float r2 = sR[qid * 4 + 2], r3 = sR[qid * 4 + 3];
    ull r0p = pk2(r0, r0), r1p = pk2(r1, r1), r2p = pk2(r2, r2), r3p = pk2(r3, r3);

    ull o0 = 0ull, o1 = 0ull, o2 = 0ull, o3 = 0ull;
    int tbeg = fpart * (FREC / 4);
    #pragma unroll 4
    for (int t = tbeg; t < tbeg + FREC / 4; ++t) {
        ulonglong2 wa = sF1[t], wb = sF2[t];
        ull hp = fma2(r0p, wa.x, sFB[t]);
        hp = fma2(r1p, wa.y, hp);
        hp = fma2(r2p, wb.x, hp);
        hp = fma2(r3p, wb.y, hp);
        float2 hh = upk2(hp);
        ull hr = pk2(fmaxf(hh.x, 0.f), fmaxf(hh.y, 0.f));
        ulonglong2 va = sF3[t], vb = sF4[t];
        o0 = fma2(hr, va.x, o0);
        o1 = fma2(hr, va.y, o1);
        o2 = fma2(hr, vb.x, o2);
        o3 = fma2(hr, vb.y, o3);
    }
    float fo0 = hsum2(o0), fo1 = hsum2(o1), fo2 = hsum2(o2), fo3 = hsum2(o3);

    if (fpart) {
        float* dst = pRed + (fpart - 1) * (TILE * 5) + qid * 5;
        dst[0] = fo0; dst[1] = fo1; dst[2] = fo2; dst[3] = fo3;
    }
    __syncthreads();   // (D) ffn partials visible
    if (!fpart) {
        #pragma unroll
        for (int p = 0; p < 3; ++p) {
            const float* src = pRed + p * (TILE * 5) + qid * 5;
            fo0 += src[0]; fo1 += src[1]; fo2 += src[2]; fo3 += src[3];
        }
        float h2[4];
        h2[0] = r0 + fo0 + b2[LAYER * 4 + 0];
        h2[1] = r1 + fo1 + b2[LAYER * 4 + 1];
        h2[2] = r2 + fo2 + b2[LAYER * 4 + 2];
        h2[3] = r3 + fo3 + b2[LAYER * 4 + 3];
        ln4(h2, g2, be2, LAYER);

        int q = base + tile0 + qid;
        if (LAYER == 0) {
            float4 nx = make_float4(h2[0], h2[1], h2[2], h2[3]);
            d_X[q] = nx;
            d_c[q] = cfeat(sCs[1], nx);
        } else {
            out[q] = fmaf(h2[0], Wfc[0], fmaf(h2[1], Wfc[1],
                     fmaf(h2[2], Wfc[2], fmaf(h2[3], Wfc[3], bfc[0]))));
        }
    }
}

extern "C" void kernel_launch(void* const* d_in, const int* in_sizes, int n_in,
                              void* d_out, int out_size)
{
    const float* KEY   = (const float*)d_in[0];
    const float* VALUE = (const float*)d_in[1];
    const float* Wq    = (const float*)d_in[2];
    const float* bq    = (const float*)d_in[3];
    const float* Wk    = (const float*)d_in[4];
    const float* bk    = (const float*)d_in[5];
    const float* Wv    = (const float*)d_in[6];
    const float* bv    = (const float*)d_in[7];
    const float* Wo    = (const float*)d_in[8];
    const float* bo    = (const float*)d_in[9];
    const float* bw    = (const float*)d_in[10];
    const float* g1    = (const float*)d_in[11];
    const float* be1   = (const float*)d_in[12];
    const float* W1    = (const float*)d_in[13];
    const float* b1    = (const float*)d_in[14];
    const float* W2    = (const float*)d_in[15];
    const float* b2    = (const float*)d_in[16];
    const float* g2    = (const float*)d_in[17];
    const float* be2   = (const float*)d_in[18];
    const float* Wfc   = (const float*)d_in[19];
    const float* bfc   = (const float*)d_in[20];

    k_att<0><<<dim3(SLEN / TILE, NB), 128>>>(KEY, VALUE, nullptr,
        Wq, bq, Wk, bk, Wv, bv, Wo, bo, bw,
        g1, be1, W1, b1, W2, b2, g2, be2, Wfc, bfc);
    k_att<1><<<dim3(SLEN / TILE, NB), 128>>>(KEY, VALUE, (float*)d_out,
        Wq, bq, Wk, bk, Wv, bv, Wo, bo, bw,
        g1, be1, W1, b1, W2, b2, g2, be2, Wfc, bfc);
}